// round 15
// baseline (speedup 1.0000x reference)
#include <cuda_runtime.h>
#include <cuda_bf16.h>
#include <cstdint>

#define NB 4
#define NC 256
#define NPIX 4096
#define ND 32

// ---------------- device scratch ----------------
__device__ __align__(256) __nv_bfloat16 g_q[(size_t)NB * NPIX * ND];   // [b][n][d] (pre-scaled by log2e)
__device__ __align__(256) __nv_bfloat16 g_k[(size_t)NB * NPIX * ND];   // [b][n][d]
__device__ __align__(256) __nv_bfloat16 g_v[(size_t)NB * NPIX * NC];   // [b][n][c]
__device__ __align__(256) __nv_bfloat16 g_wall[320 * NC];
__device__ __align__(256) float         g_ball[320];

// ---------------- PTX helpers ----------------
__device__ __forceinline__ uint32_t smem_u32(const void* p) {
    uint32_t a;
    asm("{ .reg .u64 t; cvta.to.shared.u64 t, %1; cvt.u32.u64 %0, t; }" : "=r"(a) : "l"(p));
    return a;
}
__device__ __forceinline__ void cp16(uint32_t dst, const void* src) {
    asm volatile("cp.async.cg.shared.global [%0], [%1], 16;" :: "r"(dst), "l"(src));
}
#define CP_COMMIT() asm volatile("cp.async.commit_group;" ::: "memory")
#define CP_WAIT1()  asm volatile("cp.async.wait_group 1;" ::: "memory")
#define CP_WAIT0()  asm volatile("cp.async.wait_group 0;" ::: "memory")

__device__ __forceinline__ void ldsm4(uint32_t r[4], uint32_t addr) {
    asm volatile("ldmatrix.sync.aligned.m8n8.x4.shared.b16 {%0,%1,%2,%3}, [%4];"
        : "=r"(r[0]), "=r"(r[1]), "=r"(r[2]), "=r"(r[3]) : "r"(addr));
}
__device__ __forceinline__ void ldsm4t(uint32_t r[4], uint32_t addr) {
    asm volatile("ldmatrix.sync.aligned.m8n8.x4.trans.shared.b16 {%0,%1,%2,%3}, [%4];"
        : "=r"(r[0]), "=r"(r[1]), "=r"(r[2]), "=r"(r[3]) : "r"(addr));
}
__device__ __forceinline__ void mma16816(float c[4], const uint32_t a[4],
                                         uint32_t b0, uint32_t b1) {
    asm volatile(
        "mma.sync.aligned.m16n8k16.row.col.f32.bf16.bf16.f32 "
        "{%0,%1,%2,%3}, {%4,%5,%6,%7}, {%8,%9}, {%0,%1,%2,%3};"
        : "+f"(c[0]), "+f"(c[1]), "+f"(c[2]), "+f"(c[3])
        : "r"(a[0]), "r"(a[1]), "r"(a[2]), "r"(a[3]), "r"(b0), "r"(b1));
}
__device__ __forceinline__ uint32_t packbf(float lo, float hi) {
    uint32_t r;
    asm("cvt.rn.satfinite.bf16x2.f32 %0, %1, %2;" : "=r"(r) : "f"(hi), "f"(lo));
    return r;
}
__device__ __forceinline__ float ex2f(float x) {
    float y;
    asm("ex2.approx.f32 %0, %1;" : "=f"(y) : "f"(x));
    return y;
}
__device__ __forceinline__ void sts32(uint32_t addr, uint32_t v) {
    asm volatile("st.shared.b32 [%0], %1;" :: "r"(addr), "r"(v) : "memory");
}

// ---------------- kernel 0: pack Wq/Wk/Wv + biases (Wq,bq scaled by log2e) ----------------
__global__ void __launch_bounds__(256)
packw(const float* __restrict__ Wq, const float* __restrict__ bq,
      const float* __restrict__ Wk, const float* __restrict__ bk,
      const float* __restrict__ Wv, const float* __restrict__ bv,
      __nv_bfloat16* __restrict__ wall, float* __restrict__ ball)
{
    const float LOG2E = 1.4426950408889634f;
    int r = blockIdx.x;
    int c = threadIdx.x;
    float wv, bvl;
    if (r < 32)       { wv = Wq[(size_t)r * NC + c] * LOG2E;  bvl = bq[r] * LOG2E; }
    else if (r < 64)  { wv = Wk[(size_t)(r - 32) * NC + c];   bvl = bk[r - 32]; }
    else              { wv = Wv[(size_t)(r - 64) * NC + c];   bvl = bv[r - 64]; }
    wall[(size_t)r * NC + c] = __float2bfloat16(wv);
    if (c == 0) ball[r] = bvl;
}

// ---------------- kernel 1: fused HMMA projection, direct fp32 x load ----------------
// A tile: x [c=256][n=64] fp32 loaded via LDG.128, converted to bf16 in regs,
// stored to XSTR smem layout (identical bytes to the old cp.async-from-bf16 path).
#define XSTR 144
#define WSTR 528
#define PSM_X 0
#define PSM_W (256 * XSTR)
#define PSM_TOTAL (PSM_W + 320 * WSTR)

__global__ void __launch_bounds__(256, 1)
proj_fused(const float* __restrict__ x,
           const __nv_bfloat16* __restrict__ wall,
           const float* __restrict__ ball,
           __nv_bfloat16* __restrict__ q,
           __nv_bfloat16* __restrict__ k,
           __nv_bfloat16* __restrict__ v,
           int b)
{
    extern __shared__ char smem[];
    const uint32_t sb = smem_u32(smem);
    const int n0  = blockIdx.x * 64;
    const int tid = threadIdx.x;
    const int w = tid >> 5, lane = tid & 31;
    const int m0  = (w >> 1) * 16;
    const int ncb = (w & 1) * 160;
    const int grp = lane >> 3, rr = lane & 7;
    const int gr = lane >> 2, lc = lane & 3;

    // W via cp.async (L2-resident after first CTAs)
    #pragma unroll
    for (int it = 0; it < 40; ++it) {
        int idx = tid + it * 256;
        int r = idx >> 5, c = idx & 31;
        cp16(sb + PSM_W + (uint32_t)r * WSTR + c * 16,
             wall + (size_t)r * NC + c * 8);
    }
    CP_COMMIT();

    // x tile fp32 -> bf16 smem (4096 float4 = 64KB read, 32KB smem written)
    const float* xg = x + ((size_t)b * NC) * NPIX + n0;
    #pragma unroll
    for (int it = 0; it < 16; ++it) {
        int idx = tid + it * 256;
        int r = idx >> 4, c = idx & 15;       // row r (channel), 16 float4 per row
        float4 vv = *reinterpret_cast<const float4*>(xg + (size_t)r * NPIX + c * 4);
        uint2 o;
        o.x = packbf(vv.x, vv.y);
        o.y = packbf(vv.z, vv.w);
        *reinterpret_cast<uint2*>(smem + PSM_X + r * XSTR + c * 8) = o;
    }
    CP_WAIT0();
    __syncthreads();

    float acc[20][4];
    #pragma unroll
    for (int j = 0; j < 20; ++j)
        #pragma unroll
        for (int i = 0; i < 4; ++i) acc[j][i] = 0.f;

    #pragma unroll 4
    for (int ks = 0; ks < 16; ++ks) {
        uint32_t af[4];
        ldsm4t(af, sb + PSM_X
                   + (uint32_t)(ks * 16 + (grp >> 1) * 8 + rr) * XSTR
                   + (m0 + (grp & 1) * 8) * 2);
        #pragma unroll
        for (int j = 0; j < 10; ++j) {
            uint32_t bfr[4];
            ldsm4(bfr, sb + PSM_W
                       + (uint32_t)(ncb + j * 16 + (grp >> 1) * 8 + rr) * WSTR
                       + ks * 32 + (grp & 1) * 16);
            mma16816(acc[2 * j],     af, bfr[0], bfr[1]);
            mma16816(acc[2 * j + 1], af, bfr[2], bfr[3]);
        }
    }

    const int row0 = n0 + m0 + gr;
    #pragma unroll
    for (int j = 0; j < 20; ++j) {
        int col = ncb + j * 8 + 2 * lc;
        float b0 = ball[col], b1 = ball[col + 1];
        uint32_t lop = packbf(acc[j][0] + b0, acc[j][1] + b1);
        uint32_t hip = packbf(acc[j][2] + b0, acc[j][3] + b1);
        if (col < 32) {
            uint32_t* dst = reinterpret_cast<uint32_t*>(q);
            size_t r0 = ((size_t)b * NPIX + row0) * ND + col;
            dst[r0 >> 1] = lop;
            dst[(r0 + 8 * ND) >> 1] = hip;
        } else if (col < 64) {
            uint32_t* dst = reinterpret_cast<uint32_t*>(k);
            size_t r0 = ((size_t)b * NPIX + row0) * ND + (col - 32);
            dst[r0 >> 1] = lop;
            dst[(r0 + 8 * ND) >> 1] = hip;
        } else {
            uint32_t* dst = reinterpret_cast<uint32_t*>(v);
            size_t r0 = ((size_t)b * NPIX + row0) * NC + (col - 64);
            dst[r0 >> 1] = lop;
            dst[(r0 + 8 * NC) >> 1] = hip;
        }
    }
}

// ---------------- kernel 2: warp-specialized flash attention (R13 winner, unchanged) ----------------
#define KSTRIDE 80
#define VSTRIDE 272                        // 128 chans * 2B + 16 pad
#define PSTRIDE 144
#define SK0 0
#define SK1 (SK0 + 64 * KSTRIDE)           // 5120
#define SV0 (SK1 + 64 * KSTRIDE)           // 10240
#define SV1 (SV0 + 64 * VSTRIDE)           // 27648
#define SP0 (SV1 + 64 * VSTRIDE)           // 45056 (also holds Q at prologue)
#define SP1 (SP0 + 64 * PSTRIDE)           // 54272
#define SL  (SP1 + 64 * PSTRIDE)           // 63488
#define SM_TOTAL (SL + 64 * 4 + 64)        // 63808 bytes (x2 CTAs = 127.6K < 228K)

__global__ void __launch_bounds__(256, 2)
attn_kernel(const float* __restrict__ x, const float* __restrict__ gamma,
            float* __restrict__ out)
{
    extern __shared__ char smem[];
    const uint32_t sb = smem_u32(smem);
    const int b     = blockIdx.z;
    const int chalf = blockIdx.y;          // 0/1: which 128 output channels
    const int n0q   = blockIdx.x * 64;
    const int tid = threadIdx.x;
    const int w = tid >> 5, lane = tid & 31;
    const int grp = lane >> 3, rr = lane & 7;
    const int gr = lane >> 2, lc = lane & 3;

    const bool isQK = (w < 4);
    const int qb = w;                 // QK: 16-query block (w 0-3)
    const int qh = (w - 4) & 1;       // PV: 32-query half
    const int cs = (w - 4) >> 1;      // PV: 64-channel quarter (of 128)

    const __nv_bfloat16* qg = g_q + ((size_t)b * NPIX + n0q) * ND;
    const __nv_bfloat16* kg = g_k + (size_t)b * NPIX * ND;
    const __nv_bfloat16* vg = g_v + (size_t)b * NPIX * NC + chalf * 128;

    // ---- prologue group: Q (into SP0 region) + K(0) ----
    {
        int r = tid >> 2, c = tid & 3;
        cp16(sb + SP0 + (uint32_t)r * PSTRIDE + c * 16, qg + (size_t)r * ND + c * 8);
        cp16(sb + SK0 + (uint32_t)r * KSTRIDE + c * 16, kg + (size_t)r * ND + c * 8);
    }
    CP_COMMIT();

    float Oacc0[8][4], Oacc1[8][4];   // PV: 2 m16 blocks x 8 n8 tiles (32q x 64c)
    #pragma unroll
    for (int i = 0; i < 8; ++i)
        #pragma unroll
        for (int j = 0; j < 4; ++j) { Oacc0[i][j] = 0.f; Oacc1[i][j] = 0.f; }
    float l_lo = 0.f, l_hi = 0.f;
    uint32_t qf[2][4];

    for (int i = 0; i <= 64; ++i) {
        // ---- issue loads: V(i) (this CTA's 128-chan slice) and K(i+1) ----
        if (i < 64) {
            const uint32_t vbufN = sb + ((i & 1) ? SV1 : SV0);
            const int v0 = i * 64;
            #pragma unroll
            for (int it = 0; it < 4; ++it) {
                int j = tid + it * 256;          // 1024 cp16: 64 rows x 16
                int r = j >> 4, c = j & 15;
                cp16(vbufN + (uint32_t)r * VSTRIDE + c * 16,
                     vg + (size_t)(v0 + r) * NC + c * 8);
            }
            if (i + 1 < 64) {
                const uint32_t kbufN = sb + (((i + 1) & 1) ? SK1 : SK0);
                const int k0 = (i + 1) * 64;
                int r = tid >> 2, c = tid & 3;
                cp16(kbufN + (uint32_t)r * KSTRIDE + c * 16,
                     kg + (size_t)(k0 + r) * ND + c * 8);
            }
        }
        CP_COMMIT();
        CP_WAIT1();        // group(i-1) done: V(i-1), K(i)
        __syncthreads();   // + P(i-1) visible; PV readers of previous bufs done

        if (isQK) {
            if (i < 64) {
                const uint32_t kbuf = sb + ((i & 1) ? SK1 : SK0);
                const uint32_t pbuf = sb + ((i & 1) ? SP1 : SP0);
                if (i == 0) {   // extract Q fragments (from SP0, before P(0) overwrite)
                    #pragma unroll
                    for (int ks = 0; ks < 2; ++ks)
                        ldsm4(qf[ks], sb + SP0
                              + (uint32_t)(qb * 16 + (grp & 1) * 8 + rr) * PSTRIDE
                              + ks * 32 + (grp >> 1) * 16);
                }
                // S = Q*K^T : 8 n8-tiles (64 keys), 2 k16 steps
                float sacc[8][4];
                #pragma unroll
                for (int a = 0; a < 8; ++a)
                    #pragma unroll
                    for (int j = 0; j < 4; ++j) sacc[a][j] = 0.f;
                #pragma unroll
                for (int ks = 0; ks < 2; ++ks) {
                    #pragma unroll
                    for (int p = 0; p < 4; ++p) {
                        uint32_t bfr[4];
                        ldsm4(bfr, kbuf
                              + (uint32_t)(p * 16 + (grp >> 1) * 8 + rr) * KSTRIDE
                              + ks * 32 + (grp & 1) * 16);
                        mma16816(sacc[2 * p],     qf[ks], bfr[0], bfr[1]);
                        mma16816(sacc[2 * p + 1], qf[ks], bfr[2], bfr[3]);
                    }
                }
                // exp -> P smem (bf16), accumulate l
                const uint32_t prow0 = pbuf + (uint32_t)(qb * 16 + gr) * PSTRIDE;
                #pragma unroll
                for (int nt = 0; nt < 8; ++nt) {
                    float e0 = ex2f(sacc[nt][0]);
                    float e1 = ex2f(sacc[nt][1]);
                    float e2 = ex2f(sacc[nt][2]);
                    float e3 = ex2f(sacc[nt][3]);
                    l_lo += e0 + e1;
                    l_hi += e2 + e3;
                    uint32_t jb = (uint32_t)(nt * 16 + lc * 4);
                    sts32(prow0 + jb,                packbf(e0, e1));
                    sts32(prow0 + 8 * PSTRIDE + jb,  packbf(e2, e3));
                }
            }
        } else {
            if (i >= 1) {
                const uint32_t pbuf = sb + (((i - 1) & 1) ? SP1 : SP0);
                const uint32_t vbuf = sb + (((i - 1) & 1) ? SV1 : SV0);
                // O += P * V : 32 rows x 64 chans; V fragments shared by 2 m-blocks
                #pragma unroll
                for (int kb = 0; kb < 4; ++kb) {
                    uint32_t pf0[4], pf1[4];
                    ldsm4(pf0, pbuf
                          + (uint32_t)(qh * 32 + (grp & 1) * 8 + rr) * PSTRIDE
                          + kb * 32 + (grp >> 1) * 16);
                    ldsm4(pf1, pbuf
                          + (uint32_t)(qh * 32 + 16 + (grp & 1) * 8 + rr) * PSTRIDE
                          + kb * 32 + (grp >> 1) * 16);
                    #pragma unroll
                    for (int np = 0; np < 4; ++np) {
                        uint32_t bfr[4];
                        ldsm4t(bfr, vbuf
                               + (uint32_t)(kb * 16 + (grp & 1) * 8 + rr) * VSTRIDE
                               + cs * 128 + np * 32 + (grp >> 1) * 16);
                        mma16816(Oacc0[2 * np],     pf0, bfr[0], bfr[1]);
                        mma16816(Oacc0[2 * np + 1], pf0, bfr[2], bfr[3]);
                        mma16816(Oacc1[2 * np],     pf1, bfr[0], bfr[1]);
                        mma16816(Oacc1[2 * np + 1], pf1, bfr[2], bfr[3]);
                    }
                }
            }
        }
    }

    // ---- l -> inv (QK warps), publish to smem ----
    float* L = (float*)(smem + SL);
    if (isQK) {
        l_lo += __shfl_xor_sync(0xFFFFFFFF, l_lo, 1);
        l_lo += __shfl_xor_sync(0xFFFFFFFF, l_lo, 2);
        l_hi += __shfl_xor_sync(0xFFFFFFFF, l_hi, 1);
        l_hi += __shfl_xor_sync(0xFFFFFFFF, l_hi, 2);
        if (lc == 0) {
            const float gma = gamma[0];
            L[qb * 16 + gr]     = gma / l_lo;
            L[qb * 16 + gr + 8] = gma / l_hi;
        }
    }
    __syncthreads();

    // ---- epilogue (PV warps): 2 m16 blocks x 64 chans ----
    if (!isQK) {
        #pragma unroll
        for (int mb = 0; mb < 2; ++mb) {
            const int row_lo = qh * 32 + mb * 16 + gr;
            const float inv_lo = L[row_lo];
            const float inv_hi = L[row_lo + 8];
            const int pix0 = n0q + row_lo;
            float (*Oa)[4] = mb ? Oacc1 : Oacc0;
            #pragma unroll
            for (int nt = 0; nt < 8; ++nt) {
                int c0 = chalf * 128 + cs * 64 + nt * 8 + 2 * lc;
                size_t i00 = ((size_t)b * NC + c0) * NPIX + pix0;
                size_t i01 = i00 + NPIX;
                out[i00] = Oa[nt][0] * inv_lo + x[i00];
                out[i01] = Oa[nt][1] * inv_lo + x[i01];
                size_t i10 = i00 + 8;
                size_t i11 = i01 + 8;
                out[i10] = Oa[nt][2] * inv_hi + x[i10];
                out[i11] = Oa[nt][3] * inv_hi + x[i11];
            }
        }
    }
}

// ---------------- launch (single stream, no extra resources) ----------------
extern "C" void kernel_launch(void* const* d_in, const int* in_sizes, int n_in,
                              void* d_out, int out_size)
{
    (void)in_sizes; (void)n_in; (void)out_size;
    const float* x     = (const float*)d_in[0];
    const float* Wq    = (const float*)d_in[1];
    const float* bq    = (const float*)d_in[2];
    const float* Wk    = (const float*)d_in[3];
    const float* bk    = (const float*)d_in[4];
    const float* Wv    = (const float*)d_in[5];
    const float* bv    = (const float*)d_in[6];
    const float* gamma = (const float*)d_in[7];
    float* out = (float*)d_out;

    void* p;
    cudaGetSymbolAddress(&p, g_q);    __nv_bfloat16* qT  = (__nv_bfloat16*)p;
    cudaGetSymbolAddress(&p, g_k);    __nv_bfloat16* kT  = (__nv_bfloat16*)p;
    cudaGetSymbolAddress(&p, g_v);    __nv_bfloat16* vT  = (__nv_bfloat16*)p;
    cudaGetSymbolAddress(&p, g_wall); __nv_bfloat16* wal = (__nv_bfloat16*)p;
    cudaGetSymbolAddress(&p, g_ball); float*         bal = (float*)p;

    static int attr_set = 0;
    if (!attr_set) {
        cudaFuncSetAttribute(attn_kernel,
                             cudaFuncAttributeMaxDynamicSharedMemorySize, SM_TOTAL);
        cudaFuncSetAttribute(proj_fused,
                             cudaFuncAttributeMaxDynamicSharedMemorySize, PSM_TOTAL);
        attr_set = 1;
    }

    packw<<<320, 256>>>(Wq, bq, Wk, bk, Wv, bv, wal, bal);
    for (int b = 0; b < NB; ++b)
        proj_fused<<<dim3(NPIX / 64, 1), 256, PSM_TOTAL>>>(x, wal, bal, qT, kT, vT, b);
    attn_kernel<<<dim3(NPIX / 64, 2, NB), 256, SM_TOTAL>>>(x, gamma, out);
}

// round 16
// speedup vs baseline: 1.0964x; 1.0964x over previous
#include <cuda_runtime.h>
#include <cuda_bf16.h>
#include <cstdint>

#define NB 4
#define NC 256
#define NPIX 4096
#define ND 32

// ---------------- device scratch ----------------
__device__ __align__(256) __nv_bfloat16 g_q[(size_t)NB * NPIX * ND];   // [b][n][d] (pre-scaled by log2e)
__device__ __align__(256) __nv_bfloat16 g_k[(size_t)NB * NPIX * ND];   // [b][n][d]
__device__ __align__(256) __nv_bfloat16 g_v[(size_t)NB * NPIX * NC];   // [b][n][c]
__device__ __align__(256) __nv_bfloat16 g_wall[320 * NC];
__device__ __align__(256) float         g_ball[320];

// ---------------- PTX helpers ----------------
__device__ __forceinline__ uint32_t smem_u32(const void* p) {
    uint32_t a;
    asm("{ .reg .u64 t; cvta.to.shared.u64 t, %1; cvt.u32.u64 %0, t; }" : "=r"(a) : "l"(p));
    return a;
}
__device__ __forceinline__ void cp16(uint32_t dst, const void* src) {
    asm volatile("cp.async.cg.shared.global [%0], [%1], 16;" :: "r"(dst), "l"(src));
}
#define CP_COMMIT() asm volatile("cp.async.commit_group;" ::: "memory")
#define CP_WAIT1()  asm volatile("cp.async.wait_group 1;" ::: "memory")
#define CP_WAIT0()  asm volatile("cp.async.wait_group 0;" ::: "memory")

__device__ __forceinline__ void ldsm4(uint32_t r[4], uint32_t addr) {
    asm volatile("ldmatrix.sync.aligned.m8n8.x4.shared.b16 {%0,%1,%2,%3}, [%4];"
        : "=r"(r[0]), "=r"(r[1]), "=r"(r[2]), "=r"(r[3]) : "r"(addr));
}
__device__ __forceinline__ void ldsm4t(uint32_t r[4], uint32_t addr) {
    asm volatile("ldmatrix.sync.aligned.m8n8.x4.trans.shared.b16 {%0,%1,%2,%3}, [%4];"
        : "=r"(r[0]), "=r"(r[1]), "=r"(r[2]), "=r"(r[3]) : "r"(addr));
}
__device__ __forceinline__ void mma16816(float c[4], const uint32_t a[4],
                                         uint32_t b0, uint32_t b1) {
    asm volatile(
        "mma.sync.aligned.m16n8k16.row.col.f32.bf16.bf16.f32 "
        "{%0,%1,%2,%3}, {%4,%5,%6,%7}, {%8,%9}, {%0,%1,%2,%3};"
        : "+f"(c[0]), "+f"(c[1]), "+f"(c[2]), "+f"(c[3])
        : "r"(a[0]), "r"(a[1]), "r"(a[2]), "r"(a[3]), "r"(b0), "r"(b1));
}
__device__ __forceinline__ uint32_t packbf(float lo, float hi) {
    uint32_t r;
    asm("cvt.rn.satfinite.bf16x2.f32 %0, %1, %2;" : "=r"(r) : "f"(hi), "f"(lo));
    return r;
}
__device__ __forceinline__ float ex2f(float x) {
    float y;
    asm("ex2.approx.f32 %0, %1;" : "=f"(y) : "f"(x));
    return y;
}
__device__ __forceinline__ void sts32(uint32_t addr, uint32_t v) {
    asm volatile("st.shared.b32 [%0], %1;" :: "r"(addr), "r"(v) : "memory");
}

// ---------------- kernel 0: pack Wq/Wk/Wv + biases (Wq,bq scaled by log2e) ----------------
__global__ void __launch_bounds__(256)
packw(const float* __restrict__ Wq, const float* __restrict__ bq,
      const float* __restrict__ Wk, const float* __restrict__ bk,
      const float* __restrict__ Wv, const float* __restrict__ bv,
      __nv_bfloat16* __restrict__ wall, float* __restrict__ ball)
{
    const float LOG2E = 1.4426950408889634f;
    int r = blockIdx.x;
    int c = threadIdx.x;
    float wv, bvl;
    if (r < 32)       { wv = Wq[(size_t)r * NC + c] * LOG2E;  bvl = bq[r] * LOG2E; }
    else if (r < 64)  { wv = Wk[(size_t)(r - 32) * NC + c];   bvl = bk[r - 32]; }
    else              { wv = Wv[(size_t)(r - 64) * NC + c];   bvl = bv[r - 64]; }
    wall[(size_t)r * NC + c] = __float2bfloat16(wv);
    if (c == 0) ball[r] = bvl;
}

// ---------------- kernel 1: fused HMMA projection, direct fp32 x load ----------------
// grid (NPIX/64, NB): one launch covers all batches (b = blockIdx.y).
#define XSTR 144
#define WSTR 528
#define PSM_X 0
#define PSM_W (256 * XSTR)
#define PSM_TOTAL (PSM_W + 320 * WSTR)

__global__ void __launch_bounds__(256, 1)
proj_fused(const float* __restrict__ x,
           const __nv_bfloat16* __restrict__ wall,
           const float* __restrict__ ball,
           __nv_bfloat16* __restrict__ q,
           __nv_bfloat16* __restrict__ k,
           __nv_bfloat16* __restrict__ v)
{
    extern __shared__ char smem[];
    const uint32_t sb = smem_u32(smem);
    const int b   = blockIdx.y;
    const int n0  = blockIdx.x * 64;
    const int tid = threadIdx.x;
    const int w = tid >> 5, lane = tid & 31;
    const int m0  = (w >> 1) * 16;
    const int ncb = (w & 1) * 160;
    const int grp = lane >> 3, rr = lane & 7;
    const int gr = lane >> 2, lc = lane & 3;

    // W via cp.async (L2-resident after first CTAs)
    #pragma unroll
    for (int it = 0; it < 40; ++it) {
        int idx = tid + it * 256;
        int r = idx >> 5, c = idx & 31;
        cp16(sb + PSM_W + (uint32_t)r * WSTR + c * 16,
             wall + (size_t)r * NC + c * 8);
    }
    CP_COMMIT();

    // x tile fp32 -> bf16 smem (64KB read, 32KB smem written)
    const float* xg = x + ((size_t)b * NC) * NPIX + n0;
    #pragma unroll
    for (int it = 0; it < 16; ++it) {
        int idx = tid + it * 256;
        int r = idx >> 4, c = idx & 15;       // row r (channel), 16 float4 per row
        float4 vv = *reinterpret_cast<const float4*>(xg + (size_t)r * NPIX + c * 4);
        uint2 o;
        o.x = packbf(vv.x, vv.y);
        o.y = packbf(vv.z, vv.w);
        *reinterpret_cast<uint2*>(smem + PSM_X + r * XSTR + c * 8) = o;
    }
    CP_WAIT0();
    __syncthreads();

    float acc[20][4];
    #pragma unroll
    for (int j = 0; j < 20; ++j)
        #pragma unroll
        for (int i = 0; i < 4; ++i) acc[j][i] = 0.f;

    #pragma unroll 4
    for (int ks = 0; ks < 16; ++ks) {
        uint32_t af[4];
        ldsm4t(af, sb + PSM_X
                   + (uint32_t)(ks * 16 + (grp >> 1) * 8 + rr) * XSTR
                   + (m0 + (grp & 1) * 8) * 2);
        #pragma unroll
        for (int j = 0; j < 10; ++j) {
            uint32_t bfr[4];
            ldsm4(bfr, sb + PSM_W
                       + (uint32_t)(ncb + j * 16 + (grp >> 1) * 8 + rr) * WSTR
                       + ks * 32 + (grp & 1) * 16);
            mma16816(acc[2 * j],     af, bfr[0], bfr[1]);
            mma16816(acc[2 * j + 1], af, bfr[2], bfr[3]);
        }
    }

    const int row0 = n0 + m0 + gr;
    #pragma unroll
    for (int j = 0; j < 20; ++j) {
        int col = ncb + j * 8 + 2 * lc;
        float b0 = ball[col], b1 = ball[col + 1];
        uint32_t lop = packbf(acc[j][0] + b0, acc[j][1] + b1);
        uint32_t hip = packbf(acc[j][2] + b0, acc[j][3] + b1);
        if (col < 32) {
            uint32_t* dst = reinterpret_cast<uint32_t*>(q);
            size_t r0 = ((size_t)b * NPIX + row0) * ND + col;
            dst[r0 >> 1] = lop;
            dst[(r0 + 8 * ND) >> 1] = hip;
        } else if (col < 64) {
            uint32_t* dst = reinterpret_cast<uint32_t*>(k);
            size_t r0 = ((size_t)b * NPIX + row0) * ND + (col - 32);
            dst[r0 >> 1] = lop;
            dst[(r0 + 8 * ND) >> 1] = hip;
        } else {
            uint32_t* dst = reinterpret_cast<uint32_t*>(v);
            size_t r0 = ((size_t)b * NPIX + row0) * NC + (col - 64);
            dst[r0 >> 1] = lop;
            dst[(r0 + 8 * NC) >> 1] = hip;
        }
    }
}

// ---------------- kernel 2: warp-specialized flash attention (R13 winner, unchanged) ----------------
#define KSTRIDE 80
#define VSTRIDE 272                        // 128 chans * 2B + 16 pad
#define PSTRIDE 144
#define SK0 0
#define SK1 (SK0 + 64 * KSTRIDE)           // 5120
#define SV0 (SK1 + 64 * KSTRIDE)           // 10240
#define SV1 (SV0 + 64 * VSTRIDE)           // 27648
#define SP0 (SV1 + 64 * VSTRIDE)           // 45056 (also holds Q at prologue)
#define SP1 (SP0 + 64 * PSTRIDE)           // 54272
#define SL  (SP1 + 64 * PSTRIDE)           // 63488
#define SM_TOTAL (SL + 64 * 4 + 64)        // 63808 bytes (x2 CTAs = 127.6K < 228K)

__global__ void __launch_bounds__(256, 2)
attn_kernel(const float* __restrict__ x, const float* __restrict__ gamma,
            float* __restrict__ out)
{
    extern __shared__ char smem[];
    const uint32_t sb = smem_u32(smem);
    const int b     = blockIdx.z;
    const int chalf = blockIdx.y;          // 0/1: which 128 output channels
    const int n0q   = blockIdx.x * 64;
    const int tid = threadIdx.x;
    const int w = tid >> 5, lane = tid & 31;
    const int grp = lane >> 3, rr = lane & 7;
    const int gr = lane >> 2, lc = lane & 3;

    const bool isQK = (w < 4);
    const int qb = w;                 // QK: 16-query block (w 0-3)
    const int qh = (w - 4) & 1;       // PV: 32-query half
    const int cs = (w - 4) >> 1;      // PV: 64-channel quarter (of 128)

    const __nv_bfloat16* qg = g_q + ((size_t)b * NPIX + n0q) * ND;
    const __nv_bfloat16* kg = g_k + (size_t)b * NPIX * ND;
    const __nv_bfloat16* vg = g_v + (size_t)b * NPIX * NC + chalf * 128;

    // ---- prologue group: Q (into SP0 region) + K(0) ----
    {
        int r = tid >> 2, c = tid & 3;
        cp16(sb + SP0 + (uint32_t)r * PSTRIDE + c * 16, qg + (size_t)r * ND + c * 8);
        cp16(sb + SK0 + (uint32_t)r * KSTRIDE + c * 16, kg + (size_t)r * ND + c * 8);
    }
    CP_COMMIT();

    float Oacc0[8][4], Oacc1[8][4];   // PV: 2 m16 blocks x 8 n8 tiles (32q x 64c)
    #pragma unroll
    for (int i = 0; i < 8; ++i)
        #pragma unroll
        for (int j = 0; j < 4; ++j) { Oacc0[i][j] = 0.f; Oacc1[i][j] = 0.f; }
    float l_lo = 0.f, l_hi = 0.f;
    uint32_t qf[2][4];

    for (int i = 0; i <= 64; ++i) {
        // ---- issue loads: V(i) (this CTA's 128-chan slice) and K(i+1) ----
        if (i < 64) {
            const uint32_t vbufN = sb + ((i & 1) ? SV1 : SV0);
            const int v0 = i * 64;
            #pragma unroll
            for (int it = 0; it < 4; ++it) {
                int j = tid + it * 256;          // 1024 cp16: 64 rows x 16
                int r = j >> 4, c = j & 15;
                cp16(vbufN + (uint32_t)r * VSTRIDE + c * 16,
                     vg + (size_t)(v0 + r) * NC + c * 8);
            }
            if (i + 1 < 64) {
                const uint32_t kbufN = sb + (((i + 1) & 1) ? SK1 : SK0);
                const int k0 = (i + 1) * 64;
                int r = tid >> 2, c = tid & 3;
                cp16(kbufN + (uint32_t)r * KSTRIDE + c * 16,
                     kg + (size_t)(k0 + r) * ND + c * 8);
            }
        }
        CP_COMMIT();
        CP_WAIT1();        // group(i-1) done: V(i-1), K(i)
        __syncthreads();   // + P(i-1) visible; PV readers of previous bufs done

        if (isQK) {
            if (i < 64) {
                const uint32_t kbuf = sb + ((i & 1) ? SK1 : SK0);
                const uint32_t pbuf = sb + ((i & 1) ? SP1 : SP0);
                if (i == 0) {   // extract Q fragments (from SP0, before P(0) overwrite)
                    #pragma unroll
                    for (int ks = 0; ks < 2; ++ks)
                        ldsm4(qf[ks], sb + SP0
                              + (uint32_t)(qb * 16 + (grp & 1) * 8 + rr) * PSTRIDE
                              + ks * 32 + (grp >> 1) * 16);
                }
                // S = Q*K^T : 8 n8-tiles (64 keys), 2 k16 steps
                float sacc[8][4];
                #pragma unroll
                for (int a = 0; a < 8; ++a)
                    #pragma unroll
                    for (int j = 0; j < 4; ++j) sacc[a][j] = 0.f;
                #pragma unroll
                for (int ks = 0; ks < 2; ++ks) {
                    #pragma unroll
                    for (int p = 0; p < 4; ++p) {
                        uint32_t bfr[4];
                        ldsm4(bfr, kbuf
                              + (uint32_t)(p * 16 + (grp >> 1) * 8 + rr) * KSTRIDE
                              + ks * 32 + (grp & 1) * 16);
                        mma16816(sacc[2 * p],     qf[ks], bfr[0], bfr[1]);
                        mma16816(sacc[2 * p + 1], qf[ks], bfr[2], bfr[3]);
                    }
                }
                // exp -> P smem (bf16), accumulate l
                const uint32_t prow0 = pbuf + (uint32_t)(qb * 16 + gr) * PSTRIDE;
                #pragma unroll
                for (int nt = 0; nt < 8; ++nt) {
                    float e0 = ex2f(sacc[nt][0]);
                    float e1 = ex2f(sacc[nt][1]);
                    float e2 = ex2f(sacc[nt][2]);
                    float e3 = ex2f(sacc[nt][3]);
                    l_lo += e0 + e1;
                    l_hi += e2 + e3;
                    uint32_t jb = (uint32_t)(nt * 16 + lc * 4);
                    sts32(prow0 + jb,                packbf(e0, e1));
                    sts32(prow0 + 8 * PSTRIDE + jb,  packbf(e2, e3));
                }
            }
        } else {
            if (i >= 1) {
                const uint32_t pbuf = sb + (((i - 1) & 1) ? SP1 : SP0);
                const uint32_t vbuf = sb + (((i - 1) & 1) ? SV1 : SV0);
                // O += P * V : 32 rows x 64 chans; V fragments shared by 2 m-blocks
                #pragma unroll
                for (int kb = 0; kb < 4; ++kb) {
                    uint32_t pf0[4], pf1[4];
                    ldsm4(pf0, pbuf
                          + (uint32_t)(qh * 32 + (grp & 1) * 8 + rr) * PSTRIDE
                          + kb * 32 + (grp >> 1) * 16);
                    ldsm4(pf1, pbuf
                          + (uint32_t)(qh * 32 + 16 + (grp & 1) * 8 + rr) * PSTRIDE
                          + kb * 32 + (grp >> 1) * 16);
                    #pragma unroll
                    for (int np = 0; np < 4; ++np) {
                        uint32_t bfr[4];
                        ldsm4t(bfr, vbuf
                               + (uint32_t)(kb * 16 + (grp & 1) * 8 + rr) * VSTRIDE
                               + cs * 128 + np * 32 + (grp >> 1) * 16);
                        mma16816(Oacc0[2 * np],     pf0, bfr[0], bfr[1]);
                        mma16816(Oacc0[2 * np + 1], pf0, bfr[2], bfr[3]);
                        mma16816(Oacc1[2 * np],     pf1, bfr[0], bfr[1]);
                        mma16816(Oacc1[2 * np + 1], pf1, bfr[2], bfr[3]);
                    }
                }
            }
        }
    }

    // ---- l -> inv (QK warps), publish to smem ----
    float* L = (float*)(smem + SL);
    if (isQK) {
        l_lo += __shfl_xor_sync(0xFFFFFFFF, l_lo, 1);
        l_lo += __shfl_xor_sync(0xFFFFFFFF, l_lo, 2);
        l_hi += __shfl_xor_sync(0xFFFFFFFF, l_hi, 1);
        l_hi += __shfl_xor_sync(0xFFFFFFFF, l_hi, 2);
        if (lc == 0) {
            const float gma = gamma[0];
            L[qb * 16 + gr]     = gma / l_lo;
            L[qb * 16 + gr + 8] = gma / l_hi;
        }
    }
    __syncthreads();

    // ---- epilogue (PV warps): 2 m16 blocks x 64 chans ----
    if (!isQK) {
        #pragma unroll
        for (int mb = 0; mb < 2; ++mb) {
            const int row_lo = qh * 32 + mb * 16 + gr;
            const float inv_lo = L[row_lo];
            const float inv_hi = L[row_lo + 8];
            const int pix0 = n0q + row_lo;
            float (*Oa)[4] = mb ? Oacc1 : Oacc0;
            #pragma unroll
            for (int nt = 0; nt < 8; ++nt) {
                int c0 = chalf * 128 + cs * 64 + nt * 8 + 2 * lc;
                size_t i00 = ((size_t)b * NC + c0) * NPIX + pix0;
                size_t i01 = i00 + NPIX;
                out[i00] = Oa[nt][0] * inv_lo + x[i00];
                out[i01] = Oa[nt][1] * inv_lo + x[i01];
                size_t i10 = i00 + 8;
                size_t i11 = i01 + 8;
                out[i10] = Oa[nt][2] * inv_hi + x[i10];
                out[i11] = Oa[nt][3] * inv_hi + x[i11];
            }
        }
    }
}

// ---------------- launch (single stream) ----------------
extern "C" void kernel_launch(void* const* d_in, const int* in_sizes, int n_in,
                              void* d_out, int out_size)
{
    (void)in_sizes; (void)n_in; (void)out_size;
    const float* x     = (const float*)d_in[0];
    const float* Wq    = (const float*)d_in[1];
    const float* bq    = (const float*)d_in[2];
    const float* Wk    = (const float*)d_in[3];
    const float* bk    = (const float*)d_in[4];
    const float* Wv    = (const float*)d_in[5];
    const float* bv    = (const float*)d_in[6];
    const float* gamma = (const float*)d_in[7];
    float* out = (float*)d_out;

    void* p;
    cudaGetSymbolAddress(&p, g_q);    __nv_bfloat16* qT  = (__nv_bfloat16*)p;
    cudaGetSymbolAddress(&p, g_k);    __nv_bfloat16* kT  = (__nv_bfloat16*)p;
    cudaGetSymbolAddress(&p, g_v);    __nv_bfloat16* vT  = (__nv_bfloat16*)p;
    cudaGetSymbolAddress(&p, g_wall); __nv_bfloat16* wal = (__nv_bfloat16*)p;
    cudaGetSymbolAddress(&p, g_ball); float*         bal = (float*)p;

    static int attr_set = 0;
    if (!attr_set) {
        cudaFuncSetAttribute(attn_kernel,
                             cudaFuncAttributeMaxDynamicSharedMemorySize, SM_TOTAL);
        cudaFuncSetAttribute(proj_fused,
                             cudaFuncAttributeMaxDynamicSharedMemorySize, PSM_TOTAL);
        attr_set = 1;
    }

    packw<<<320, 256>>>(Wq, bq, Wk, bk, Wv, bv, wal, bal);
    proj_fused<<<dim3(NPIX / 64, NB), 256, PSM_TOTAL>>>(x, wal, bal, qT, kT, vT);
    attn_kernel<<<dim3(NPIX / 64, 2, NB), 256, SM_TOTAL>>>(x, gamma, out);
}